// round 7
// baseline (speedup 1.0000x reference)
#include <cuda_runtime.h>
#include <cuda_bf16.h>
#include <cstdint>

// ---------------- problem constants ----------------
#define BS      2
#define C_IN    64
#define NA      60
#define KS      3
#define ANN     8
#define C_OUT   128
#define K_DIM   192              // C_IN*KS
#define NPAIRS  180              // NA*KS
#define NP      1024
#define NJOBS   (BS * NP)        // 2048

#define KSTEPS  12               // 192 / 16
#define NTILES  8                // 64 / 8

// G fragment units: [nt 8][ks 12][lane 32] x 16B; element u32 = bf16 hi | lo<<16
#define UNITS_PER_JOB (NTILES * KSTEPS * 32)      // 3072 units = 49152 B
#define G_U4_PER_JOB  UNITS_PER_JOB

// ---------------- k1 smem ----------------
#define FPAD        61
#define K1_B_BYTES  (UNITS_PER_JOB * 16)          // 49152
#define K1_SMEM_F   K1_B_BYTES
#define K1_SMEM_TOTAL (K1_SMEM_F + C_IN * FPAD * 4)   // 64768 -> 3 CTAs/SM

// ---------------- global staging ----------------
// A fragments (W) in HMMA per-lane order: [part hi/lo][mtile 8][kstep 12][lane 32][4 x b32]
__device__ __align__(16) uint32_t Afrag_g[2 * 8 * KSTEPS * 32 * 4];   // 96 KB
// G fragments (gather output) for all jobs (~100.7 MB, static scratch)
__device__ __align__(16) uint4 G_g[(size_t)NJOBS * G_U4_PER_JOB];

__global__ void pack_W_kernel(const float* __restrict__ Wmat) {
    int t = blockIdx.x * 256 + threadIdx.x;          // t = ((part*8+mt)*12+ks)*32+lane
    if (t >= 2 * 8 * KSTEPS * 32) return;
    const int lane = t & 31;
    const int ks   = (t >> 5) % KSTEPS;
    const int mt   = (t >> 5) / KSTEPS % 8;
    const int part = t / (32 * KSTEPS * 8);          // 0 = hi, 1 = lo
    const int r0 = mt * 16 + (lane >> 2);
    const int k0 = ks * 16 + ((lane & 3) << 1);

    uint32_t regs[4];
    #pragma unroll
    for (int reg = 0; reg < 4; reg++) {
        const int r = r0 + ((reg & 1) ? 8 : 0);
        const int k = k0 + ((reg & 2) ? 8 : 0);
        float f0 = Wmat[r * K_DIM + k];
        float f1 = Wmat[r * K_DIM + k + 1];
        __nv_bfloat16 h0 = __float2bfloat16_rn(f0);
        __nv_bfloat16 h1 = __float2bfloat16_rn(f1);
        __nv_bfloat16 v0, v1;
        if (part == 0) { v0 = h0; v1 = h1; }
        else {
            v0 = __float2bfloat16_rn(f0 - __bfloat162float(h0));
            v1 = __float2bfloat16_rn(f1 - __bfloat162float(h1));
        }
        regs[reg] = (uint32_t)__bfloat16_as_ushort(v0) |
                    ((uint32_t)__bfloat16_as_ushort(v1) << 16);
    }
    *(uint4*)(Afrag_g + (size_t)t * 4) = make_uint4(regs[0], regs[1], regs[2], regs[3]);
}

// byte offset of the u32 (hi|lo) for logical (o = n index, kc = k index)
__device__ __forceinline__ uint32_t bfrag_off32(int o, int kc) {
    const uint32_t u = (uint32_t)((((o >> 3) * KSTEPS + (kc >> 4)) * 32) +
                                  ((o & 7) << 2) + ((kc >> 1) & 3));
    return (u << 4) + ((((uint32_t)kc >> 3) & 1) << 3) + (((uint32_t)kc & 1) << 2);
}

__device__ __forceinline__ uint32_t smem_u32(const void* p) {
    uint32_t a;
    asm("{ .reg .u64 t; cvta.to.shared.u64 t, %1; cvt.u32.u64 %0, t; }" : "=r"(a) : "l"(p));
    return a;
}

__device__ __forceinline__ void mma_bf16(float* c, const uint4 a, uint32_t b0, uint32_t b1) {
    asm volatile(
        "mma.sync.aligned.m16n8k16.row.col.f32.bf16.bf16.f32 "
        "{%0,%1,%2,%3}, {%4,%5,%6,%7}, {%8,%9}, {%0,%1,%2,%3};"
        : "+f"(c[0]), "+f"(c[1]), "+f"(c[2]), "+f"(c[3])
        : "r"(a.x), "r"(a.y), "r"(a.z), "r"(a.w), "r"(b0), "r"(b1));
}

// ================= kernel 1: gather -> G fragments =================
__global__ __launch_bounds__(256, 3)
void gather_kernel(const float* __restrict__ feats,
                   const float* __restrict__ intra_w,
                   const int*   __restrict__ intra_idx)
{
    extern __shared__ char smem[];
    const uint32_t smb = smem_u32(smem);
    float* Fsm = (float*)(smem + K1_SMEM_F);
    const int tid = threadIdx.x, wid = tid >> 5, lane = tid & 31;
    const int job = blockIdx.x, b = job >> 10, p = job & (NP - 1);

    // zero pad rows o = 60..63 (one u32 covers hi+lo)
    for (int t = tid; t < 4 * K_DIM; t += 256) {
        const int o = 60 + t / K_DIM, kc = t % K_DIM;
        asm volatile("st.shared.u32 [%0], %1;" :: "r"(smb + bfrag_off32(o, kc)), "r"(0u));
    }
    // feats slab (64 x 60) as float4
    for (int t = tid; t < C_IN * 15; t += 256) {
        const int c = t / 15, q = t - c * 15;
        const float4 v = __ldg((const float4*)(feats +
                          (((size_t)b * C_IN + c) * NP + p) * NA) + q);
        float* dst = Fsm + c * FPAD + q * 4;
        dst[0] = v.x; dst[1] = v.y; dst[2] = v.z; dst[3] = v.w;
    }
    __syncthreads();

    // gather-reduce: warp per (o,k) pair; idx/w via vectorized uniform LDG
    for (int pr = wid; pr < NPAIRS; pr += 8) {
        const int o = pr / KS, kk = pr - o * KS;
        const int4   ia = __ldg((const int4*)(intra_idx + pr * ANN));
        const int4   ib = __ldg((const int4*)(intra_idx + pr * ANN) + 1);
        const float4 wa = __ldg((const float4*)(intra_w + pr * ANN));
        const float4 wb = __ldg((const float4*)(intra_w + pr * ANN) + 1);
        #pragma unroll
        for (int half = 0; half < 2; half++) {
            const int c = half * 32 + lane;
            const float* fr = Fsm + c * FPAD;
            float acc = fr[ia.x] * wa.x;
            acc = fmaf(fr[ia.y], wa.y, acc);
            acc = fmaf(fr[ia.z], wa.z, acc);
            acc = fmaf(fr[ia.w], wa.w, acc);
            acc = fmaf(fr[ib.x], wb.x, acc);
            acc = fmaf(fr[ib.y], wb.y, acc);
            acc = fmaf(fr[ib.z], wb.z, acc);
            acc = fmaf(fr[ib.w], wb.w, acc);
            const __nv_bfloat16 h = __float2bfloat16_rn(acc);
            const __nv_bfloat16 l = __float2bfloat16_rn(acc - __bfloat162float(h));
            const uint32_t v = (uint32_t)__bfloat16_as_ushort(h) |
                               ((uint32_t)__bfloat16_as_ushort(l) << 16);
            asm volatile("st.shared.u32 [%0], %1;"
                         :: "r"(smb + bfrag_off32(o, c * KS + kk)), "r"(v));
        }
    }
    __syncthreads();

    // coalesced copyout to G
    const uint4* src = (const uint4*)smem;
    uint4* dst = G_g + (size_t)job * G_U4_PER_JOB;
    #pragma unroll
    for (int t = tid; t < G_U4_PER_JOB; t += 256) dst[t] = src[t];
}

// ================= kernel 2: paired GEMM =================
// CTA handles 2 jobs; 8 warps = 4(mq rows) x 2(jq job); warp tile 32M x 64N.
__global__ __launch_bounds__(256, 2)
void gemm_kernel(const float* __restrict__ bias, float* __restrict__ out)
{
    const int tid = threadIdx.x, wid = tid >> 5, lane = tid & 31;
    const int mq = wid & 3, jq = wid >> 2;
    const int job = blockIdx.x * 2 + jq;
    const int b = job >> 10, p = job & (NP - 1);

    float bv[4];
    #pragma unroll
    for (int i = 0; i < 4; i++) bv[i] = __ldg(bias + mq * 32 + (lane >> 2) + i * 8);

    float acc[2][NTILES][4];
    #pragma unroll
    for (int mt = 0; mt < 2; mt++)
        #pragma unroll
        for (int nt = 0; nt < NTILES; nt++) {
            acc[mt][nt][0] = bv[2 * mt];     acc[mt][nt][1] = bv[2 * mt];
            acc[mt][nt][2] = bv[2 * mt + 1]; acc[mt][nt][3] = bv[2 * mt + 1];
        }

    const uint4* Gj = G_g + (size_t)job * G_U4_PER_JOB;
    const int mt0 = mq * 2;

    #pragma unroll
    for (int ks = 0; ks < KSTEPS; ks++) {
        uint4 ah[2], al[2];
        #pragma unroll
        for (int mt = 0; mt < 2; mt++) {
            ah[mt] = __ldg((const uint4*)Afrag_g + ((0 + mt0 + mt) * KSTEPS + ks) * 32 + lane);
            al[mt] = __ldg((const uint4*)Afrag_g + ((8 + mt0 + mt) * KSTEPS + ks) * 32 + lane);
        }
        #pragma unroll
        for (int nt = 0; nt < NTILES; nt++) {
            const uint4 g = __ldg(Gj + (nt * KSTEPS + ks) * 32 + lane);
            uint32_t bh0, bh1, bl0, bl1;
            asm("prmt.b32 %0, %1, %2, 0x5410;" : "=r"(bh0) : "r"(g.x), "r"(g.y));
            asm("prmt.b32 %0, %1, %2, 0x7632;" : "=r"(bl0) : "r"(g.x), "r"(g.y));
            asm("prmt.b32 %0, %1, %2, 0x5410;" : "=r"(bh1) : "r"(g.z), "r"(g.w));
            asm("prmt.b32 %0, %1, %2, 0x7632;" : "=r"(bl1) : "r"(g.z), "r"(g.w));
            #pragma unroll
            for (int mt = 0; mt < 2; mt++) {
                mma_bf16(acc[mt][nt], ah[mt], bh0, bh1);   // hi*hi
                mma_bf16(acc[mt][nt], ah[mt], bl0, bl1);   // hi*lo
                mma_bf16(acc[mt][nt], al[mt], bh0, bh1);   // lo*hi
            }
        }
    }

    // epilogue
    const int ncol = (lane & 3) * 2;
    #pragma unroll
    for (int mt = 0; mt < 2; mt++) {
        const int r1 = mq * 32 + mt * 16 + (lane >> 2);
        float* orow1 = out + (((size_t)(b * C_OUT + r1)) * NP + p) * NA;
        float* orow2 = orow1 + (size_t)8 * NP * NA;
        #pragma unroll
        for (int nt = 0; nt < NTILES; nt++) {
            const int n = ncol + nt * 8;
            if (n < NA) {
                *(float2*)(orow1 + n) = make_float2(acc[mt][nt][0], acc[mt][nt][1]);
                *(float2*)(orow2 + n) = make_float2(acc[mt][nt][2], acc[mt][nt][3]);
            }
        }
    }
}

extern "C" void kernel_launch(void* const* d_in, const int* in_sizes, int n_in,
                              void* d_out, int out_size)
{
    const float* feats     = (const float*)d_in[0];  // (2,64,1024,60) f32
    const float* intra_w   = (const float*)d_in[1];  // (60,3,8)       f32
    const float* Wmat      = (const float*)d_in[2];  // (128,192)      f32
    const float* bias      = (const float*)d_in[3];  // (1,128,1)      f32
    const int*   intra_idx = (const int*)  d_in[4];  // (60,3,8)       i32
    float* out = (float*)d_out;                      // (2,128,1024,60) f32

    cudaFuncSetAttribute(gather_kernel,
                         cudaFuncAttributeMaxDynamicSharedMemorySize, K1_SMEM_TOTAL);

    pack_W_kernel<<<(2 * 8 * KSTEPS * 32 + 255) / 256, 256>>>(Wmat);
    gather_kernel<<<NJOBS, 256, K1_SMEM_TOTAL>>>(feats, intra_w, intra_idx);
    gemm_kernel<<<NJOBS / 2, 256>>>(bias, out);
}

// round 8
// speedup vs baseline: 1.5296x; 1.5296x over previous
#include <cuda_runtime.h>
#include <cuda_bf16.h>
#include <cstdint>

// ---------------- problem constants ----------------
#define BS      2
#define C_IN    64
#define NA      60
#define KS      3
#define ANN     8
#define C_OUT   128
#define K_DIM   192              // C_IN*KS
#define NPAIRS  180              // NA*KS
#define NP      1024
#define NJOBS   (BS * NP)        // 2048

#define NTHREADS 256
#define GRID_CTAS 296            // 2 per SM x 148 SMs

#define KSTEPS  12               // 192 / 16
#define NTILES  8                // 64 / 8

// ---------------- SMEM layout (bytes) ----------------
// B fragments: packed u32 per element (bf16 hi | lo<<16).
// 16B unit u = (nt*KSTEPS + ks)*32 + lane holds 4 u32:
//   [0]=k-even half0, [1]=k-odd half0, [2]=k-even half1, [3]=k-odd half1
#define B_BYTES     (NTILES * KSTEPS * 32 * 16)      // 49152
#define SMEM_B      0
#define FPAD        61
#define SMEM_F      B_BYTES                          // 49152
#define SMEM_IDX    (SMEM_F + C_IN * FPAD * 4)       // 64768 (16B aligned)
#define SMEM_WV     (SMEM_IDX + NPAIRS * ANN * 4)    // 70528
#define SMEM_TOTAL  (SMEM_WV + NPAIRS * ANN * 4)     // 76288

// ---------------- A fragments (W) in HMMA per-lane order ----------------
// [part hi/lo][mtile 8][kstep 12][lane 32][4 x b32]
__device__ __align__(16) uint32_t Afrag_g[2 * 8 * KSTEPS * 32 * 4];   // 96 KB

__global__ void pack_W_kernel(const float* __restrict__ Wmat) {
    int t = blockIdx.x * 256 + threadIdx.x;          // t = ((part*8+mt)*12+ks)*32+lane
    if (t >= 2 * 8 * KSTEPS * 32) return;
    const int lane = t & 31;
    const int ks   = (t >> 5) % KSTEPS;
    const int mt   = (t >> 5) / KSTEPS % 8;
    const int part = t / (32 * KSTEPS * 8);          // 0 = hi, 1 = lo
    const int r0 = mt * 16 + (lane >> 2);
    const int k0 = ks * 16 + ((lane & 3) << 1);

    uint32_t regs[4];
    #pragma unroll
    for (int reg = 0; reg < 4; reg++) {
        const int r = r0 + ((reg & 1) ? 8 : 0);
        const int k = k0 + ((reg & 2) ? 8 : 0);
        float f0 = Wmat[r * K_DIM + k];
        float f1 = Wmat[r * K_DIM + k + 1];
        __nv_bfloat16 h0 = __float2bfloat16_rn(f0);
        __nv_bfloat16 h1 = __float2bfloat16_rn(f1);
        __nv_bfloat16 v0, v1;
        if (part == 0) { v0 = h0; v1 = h1; }
        else {
            v0 = __float2bfloat16_rn(f0 - __bfloat162float(h0));
            v1 = __float2bfloat16_rn(f1 - __bfloat162float(h1));
        }
        regs[reg] = (uint32_t)__bfloat16_as_ushort(v0) |
                    ((uint32_t)__bfloat16_as_ushort(v1) << 16);
    }
    *(uint4*)(Afrag_g + (size_t)t * 4) = make_uint4(regs[0], regs[1], regs[2], regs[3]);
}

// byte offset of the packed u32 for logical (o = n index, kc = k index)
__device__ __forceinline__ uint32_t bfrag_off32(int o, int kc) {
    const uint32_t u = (uint32_t)((((o >> 3) * KSTEPS + (kc >> 4)) * 32) +
                                  ((o & 7) << 2) + ((kc >> 1) & 3));
    return (u << 4) + ((((uint32_t)kc >> 3) & 1) << 3) + (((uint32_t)kc & 1) << 2);
}

__device__ __forceinline__ uint32_t smem_u32(const void* p) {
    uint32_t a;
    asm("{ .reg .u64 t; cvta.to.shared.u64 t, %1; cvt.u32.u64 %0, t; }" : "=r"(a) : "l"(p));
    return a;
}

__device__ __forceinline__ void mma_bf16(float* c, const uint4 a, uint32_t b0, uint32_t b1) {
    asm volatile(
        "mma.sync.aligned.m16n8k16.row.col.f32.bf16.bf16.f32 "
        "{%0,%1,%2,%3}, {%4,%5,%6,%7}, {%8,%9}, {%0,%1,%2,%3};"
        : "+f"(c[0]), "+f"(c[1]), "+f"(c[2]), "+f"(c[3])
        : "r"(a.x), "r"(a.y), "r"(a.z), "r"(a.w), "r"(b0), "r"(b1));
}

// ---------------- main fused kernel (persistent, 2 CTAs/SM) ----------------
__global__ __launch_bounds__(NTHREADS, 2)
void intrazp_mma_kernel(const float* __restrict__ feats,
                        const float* __restrict__ intra_w,
                        const float* __restrict__ bias,
                        const int*   __restrict__ intra_idx,
                        float* __restrict__ out)
{
    extern __shared__ char smem[];
    const uint32_t smb = smem_u32(smem);
    float* Fsm  = (float*)(smem + SMEM_F);
    int*   Ism  = (int*)  (smem + SMEM_IDX);
    float* Wvsm = (float*)(smem + SMEM_WV);
    const int tid = threadIdx.x, wid = tid >> 5, lane = tid & 31;

    // warp tiling for GEMM: 4M x 2N; warp covers rows [32*mq, +32), cols [32*nq, +32)
    const int mq = wid & 3, nq = wid >> 2;

    // ---- one-time: zero B pad rows (o = 60..63), cache idx/w in smem ----
    for (int t = tid; t < 4 * K_DIM; t += NTHREADS) {
        const int o = 60 + t / K_DIM, kc = t % K_DIM;
        asm volatile("st.shared.u32 [%0], %1;"
                     :: "r"(smb + SMEM_B + bfrag_off32(o, kc)), "r"(0u));
    }
    for (int t = tid; t < NPAIRS * ANN; t += NTHREADS) {
        Ism[t]  = __ldg(intra_idx + t);
        Wvsm[t] = __ldg(intra_w + t);
    }

    // bias for the 4 row-groups this thread accumulates
    const int rb = mq * 32 + (lane >> 2);
    float bv[4];
    #pragma unroll
    for (int i = 0; i < 4; i++) bv[i] = __ldg(bias + rb + i * 8);
    __syncthreads();

    for (int job = blockIdx.x; job < NJOBS; job += GRID_CTAS) {
        const int b = job >> 10, p = job & (NP - 1);

        // ---- load feats slab (64 x 60) as float4 ----
        for (int t = tid; t < C_IN * 15; t += NTHREADS) {
            const int c = t / 15, q = t - c * 15;
            const float4 v = __ldg((const float4*)(feats +
                              (((size_t)b * C_IN + c) * NP + p) * NA) + q);
            float* dst = Fsm + c * FPAD + q * 4;
            dst[0] = v.x; dst[1] = v.y; dst[2] = v.z; dst[3] = v.w;
        }
        __syncthreads();

        // ---- stage A: gather-reduce -> packed bf16 hi|lo B fragments ----
        for (int pr = wid; pr < NPAIRS; pr += 8) {
            const int o = pr / KS, kk = pr - o * KS;
            // vectorized uniform reads from smem cache (LDS.128 broadcasts)
            const int4   ia = *(const int4*)  (Ism  + pr * ANN);
            const int4   ib = *((const int4*) (Ism  + pr * ANN) + 1);
            const float4 wa = *(const float4*)(Wvsm + pr * ANN);
            const float4 wb = *((const float4*)(Wvsm + pr * ANN) + 1);
            #pragma unroll
            for (int half = 0; half < 2; half++) {
                const int c = half * 32 + lane;
                const float* fr = Fsm + c * FPAD;
                float acc = fr[ia.x] * wa.x;
                acc = fmaf(fr[ia.y], wa.y, acc);
                acc = fmaf(fr[ia.z], wa.z, acc);
                acc = fmaf(fr[ia.w], wa.w, acc);
                acc = fmaf(fr[ib.x], wb.x, acc);
                acc = fmaf(fr[ib.y], wb.y, acc);
                acc = fmaf(fr[ib.z], wb.z, acc);
                acc = fmaf(fr[ib.w], wb.w, acc);
                const __nv_bfloat16 h = __float2bfloat16_rn(acc);
                const __nv_bfloat16 l = __float2bfloat16_rn(acc - __bfloat162float(h));
                const uint32_t v = (uint32_t)__bfloat16_as_ushort(h) |
                                   ((uint32_t)__bfloat16_as_ushort(l) << 16);
                asm volatile("st.shared.u32 [%0], %1;"
                             :: "r"(smb + SMEM_B + bfrag_off32(o, c * KS + kk)), "r"(v));
            }
        }
        __syncthreads();

        // ---- GEMM: fused 3-pass split (hh + hl + lh), warp tile 32M x 32N ----
        float acc[2][4][4];
        #pragma unroll
        for (int mt = 0; mt < 2; mt++)
            #pragma unroll
            for (int j = 0; j < 4; j++) {
                acc[mt][j][0] = bv[2 * mt];     acc[mt][j][1] = bv[2 * mt];
                acc[mt][j][2] = bv[2 * mt + 1]; acc[mt][j][3] = bv[2 * mt + 1];
            }

        const int mt0 = 2 * mq;
        #pragma unroll
        for (int ks = 0; ks < KSTEPS; ks++) {
            uint4 ah[2], al[2];
            #pragma unroll
            for (int mt = 0; mt < 2; mt++) {
                ah[mt] = __ldg((const uint4*)Afrag_g + ((0 + mt0 + mt) * KSTEPS + ks) * 32 + lane);
                al[mt] = __ldg((const uint4*)Afrag_g + ((8 + mt0 + mt) * KSTEPS + ks) * 32 + lane);
            }
            uint32_t bh[4][2], bl[4][2];
            #pragma unroll
            for (int j = 0; j < 4; j++) {
                const int nt = nq * 4 + j;
                uint32_t g0, g1, g2, g3;
                asm volatile("ld.shared.v4.b32 {%0,%1,%2,%3}, [%4];"
                             : "=r"(g0), "=r"(g1), "=r"(g2), "=r"(g3)
                             : "r"(smb + SMEM_B + (uint32_t)(((nt * KSTEPS + ks) * 32 + lane) << 4)));
                asm("prmt.b32 %0, %1, %2, 0x5410;" : "=r"(bh[j][0]) : "r"(g0), "r"(g1));
                asm("prmt.b32 %0, %1, %2, 0x7632;" : "=r"(bl[j][0]) : "r"(g0), "r"(g1));
                asm("prmt.b32 %0, %1, %2, 0x5410;" : "=r"(bh[j][1]) : "r"(g2), "r"(g3));
                asm("prmt.b32 %0, %1, %2, 0x7632;" : "=r"(bl[j][1]) : "r"(g2), "r"(g3));
            }
            #pragma unroll
            for (int j = 0; j < 4; j++) {
                #pragma unroll
                for (int mt = 0; mt < 2; mt++) {
                    mma_bf16(acc[mt][j], ah[mt], bh[j][0], bh[j][1]);   // hi*hi
                    mma_bf16(acc[mt][j], ah[mt], bl[j][0], bl[j][1]);   // hi*lo
                    mma_bf16(acc[mt][j], al[mt], bh[j][0], bh[j][1]);   // lo*hi
                }
            }
        }

        // ---- epilogue: store rows (2 mtiles x 2 row-groups), cols 32*nq..+31 ----
        {
            const int ncol = nq * 32 + (lane & 3) * 2;
            #pragma unroll
            for (int mt = 0; mt < 2; mt++) {
                const int r1 = mq * 32 + mt * 16 + (lane >> 2);
                float* orow1 = out + (((size_t)(b * C_OUT + r1)) * NP + p) * NA;
                float* orow2 = orow1 + (size_t)8 * NP * NA;
                #pragma unroll
                for (int j = 0; j < 4; j++) {
                    const int n = ncol + j * 8;
                    if (n < NA) {
                        *(float2*)(orow1 + n) = make_float2(acc[mt][j][0], acc[mt][j][1]);
                        *(float2*)(orow2 + n) = make_float2(acc[mt][j][2], acc[mt][j][3]);
                    }
                }
            }
        }
        __syncthreads();   // protect Fsm/B before next job
    }
}

extern "C" void kernel_launch(void* const* d_in, const int* in_sizes, int n_in,
                              void* d_out, int out_size)
{
    const float* feats     = (const float*)d_in[0];  // (2,64,1024,60) f32
    const float* intra_w   = (const float*)d_in[1];  // (60,3,8)       f32
    const float* Wmat      = (const float*)d_in[2];  // (128,192)      f32
    const float* bias      = (const float*)d_in[3];  // (1,128,1)      f32
    const int*   intra_idx = (const int*)  d_in[4];  // (60,3,8)       i32
    float* out = (float*)d_out;                      // (2,128,1024,60) f32

    cudaFuncSetAttribute(intrazp_mma_kernel,
                         cudaFuncAttributeMaxDynamicSharedMemorySize, SMEM_TOTAL);

    pack_W_kernel<<<(2 * 8 * KSTEPS * 32 + 255) / 256, 256>>>(Wmat);
    intrazp_mma_kernel<<<GRID_CTAS, NTHREADS, SMEM_TOTAL>>>(
        feats, intra_w, bias, intra_idx, out);
}